// round 11
// baseline (speedup 1.0000x reference)
#include <cuda_runtime.h>
#include <cuda_bf16.h>
#include <cstdint>

#define TRAJ      25
#define NT        10
#define NS        10
#define GDIM      200
#define GD2       (GDIM * GDIM)
#define MAP_ELEMS 8000000
#define VFOV_C    0.3490658503988659f
#define MAX_BT    (1024 * TRAJ * NT)   // supports outer up to 1024

// Interleaved staging: [n*2+0] = (pos_voxel.xyz, pen), [n*2+1] = (gdir.xyz, 0)
// Same 32B segment -> one sector for both per-thread staging loads.
__device__ float4 g_stage[MAX_BT * 2];

// ---------- kernel 1: per-(b,t) prelude ----------
__global__ __launch_bounds__(256) void prelude_kernel(
    const float* __restrict__ Df, const float* __restrict__ Dp,
    const float* __restrict__ goal, const float* __restrict__ L,
    const float* __restrict__ minb, const int* __restrict__ map_id,
    float* __restrict__ out, int n_bt)
{
    const int n = blockIdx.x * blockDim.x + threadIdx.x;
    if (n >= n_bt) return;
    const int b  = n / NT;
    const int it = n - b * NT;
    const int o  = b / TRAJ;

    const float t = 0.66f + (float)it * ((1.32f - 0.66f) / 9.0f);

    float pos[3], vel[3];
    #pragma unroll
    for (int c = 0; c < 3; c++) {
        const float d0 = __ldg(Df + b * 9 + c * 3 + 0);
        const float d1 = __ldg(Df + b * 9 + c * 3 + 1);
        const float d2 = __ldg(Df + b * 9 + c * 3 + 2);
        const float d3 = __ldg(Dp + b * 9 + c * 3 + 0);
        const float d4 = __ldg(Dp + b * 9 + c * 3 + 1);
        const float d5 = __ldg(Dp + b * 9 + c * 3 + 2);
        float coe[6];
        #pragma unroll
        for (int i = 0; i < 6; i++) {
            coe[i] = __ldg(L + i * 6 + 0) * d0 + __ldg(L + i * 6 + 1) * d1
                   + __ldg(L + i * 6 + 2) * d2 + __ldg(L + i * 6 + 3) * d3
                   + __ldg(L + i * 6 + 4) * d4 + __ldg(L + i * 6 + 5) * d5;
        }
        float p = coe[5];
        p = p * t + coe[4];
        p = p * t + coe[3];
        p = p * t + coe[2];
        p = p * t + coe[1];
        p = p * t + coe[0];
        pos[c] = p;
        float v = 5.0f * coe[5];
        v = v * t + 4.0f * coe[4];
        v = v * t + 3.0f * coe[3];
        v = v * t + 2.0f * coe[2];
        v = v * t + coe[1];
        vel[c] = v;
    }

    const float gx0 = __ldg(goal + (long long)o * TRAJ * 3 + 0);
    const float gy0 = __ldg(goal + (long long)o * TRAJ * 3 + 1);
    const float gz0 = __ldg(goal + (long long)o * TRAJ * 3 + 2);
    const float gdx = gx0 - pos[0];
    const float gdy = gy0 - pos[1];
    const float gdz = gz0 - pos[2];

    const float pg = atan2f(gdz, sqrtf(gdx * gdx + gdy * gdy + 1e-6f));
    const float pv = atan2f(vel[2], sqrtf(vel[0] * vel[0] + vel[1] * vel[1] + 1e-6f));
    const float pen = fmaxf(fabsf(pg - pv) - VFOV_C, 0.0f);

    const int   m   = __ldg(map_id + o);
    const float mb0 = __ldg(minb + m * 3 + 0);
    const float mb1 = __ldg(minb + m * 3 + 1);
    const float mb2 = __ldg(minb + m * 3 + 2);

    g_stage[n * 2 + 0] = make_float4((pos[0] - mb0) * 5.0f,
                                     (pos[1] - mb1) * 5.0f,
                                     (pos[2] - mb2) * 5.0f, pen);
    g_stage[n * 2 + 1] = make_float4(gdx * 5.0f, gdy * 5.0f, gdz * 5.0f, 0.0f);

    if (it == 0) out[b] = 0.0f;   // zero-init before gather kernel's atomics
}

// ---------- kernel 2: TWO vectorized trilinear samples per thread ----------
// grid (NS/2, outer): x = s-half (consecutive blocks share the outer group's
// map -> L2 temporal locality). tid<250 -> (traj j, time it).
// No residency cap: ~5 blocks/SM at ~50 regs, 9-10 independent lines/thread.
__global__ __launch_bounds__(256) void gather_kernel(
    const float* __restrict__ sdf, const int* __restrict__ map_id,
    float* __restrict__ out)
{
    const int s0  = blockIdx.x;          // samples s0 and s0+5
    const int o   = blockIdx.y;
    const int tid = threadIdx.x;

    __shared__ float sC[TRAJ * NT];

    float w = 0.0f;
    if (tid < TRAJ * NT) {
        const int n = (o * TRAJ) * NT + tid;

        const float4 p4 = __ldg(g_stage + n * 2 + 0);
        const float4 g4 = __ldg(g_stage + n * 2 + 1);

        const float* __restrict__ map =
            sdf + (long long)__ldg(map_id + o) * MAP_ELEMS;

        // --- coordinates / aligned bases for both samples ---
        float fx[2], fy[2], fz[2];
        bool  valid[2];
        int   ab[2], ph[2];
        #pragma unroll
        for (int k = 0; k < 2; k++) {
            const float a  = (float)(s0 + 5 * k) * (1.0f / 9.0f);
            const float vx = p4.x + a * g4.x;
            const float vy = p4.y + a * g4.y;
            const float vz = p4.z + a * g4.z;
            valid[k] = (vx > 0.5f) && (vx < (float)GDIM - 1.5f)
                    && (vy > 0.5f) && (vy < (float)GDIM - 1.5f)
                    && (vz > 0.5f) && (vz < (float)GDIM - 1.5f);
            const float x0f = fminf(fmaxf(floorf(vx), 0.0f), (float)(GDIM - 2));
            const float y0f = fminf(fmaxf(floorf(vy), 0.0f), (float)(GDIM - 2));
            const float z0f = fminf(fmaxf(floorf(vz), 0.0f), (float)(GDIM - 2));
            fx[k] = vx - x0f; fy[k] = vy - y0f; fz[k] = vz - z0f;
            const int x0 = valid[k] ? (int)x0f : 0;
            const int y0 = valid[k] ? (int)y0f : 0;
            const int z0 = valid[k] ? (int)z0f : 0;
            ph[k] = x0 & 3;
            ab[k] = z0 * GD2 + y0 * GDIM + (x0 & ~3);
        }

        // --- issue ALL vector gathers for both samples back-to-back ---
        float4 q[2][4];
        float  ex[2][4];
        #pragma unroll
        for (int k = 0; k < 2; k++) {
            q[k][0] = __ldg((const float4*)(map + ab[k]));
            q[k][1] = __ldg((const float4*)(map + ab[k] + GDIM));
            q[k][2] = __ldg((const float4*)(map + ab[k] + GD2));
            q[k][3] = __ldg((const float4*)(map + ab[k] + GD2 + GDIM));
        }
        #pragma unroll
        for (int k = 0; k < 2; k++) {
            const bool need = (ph[k] == 3);
            ex[k][0] = need ? __ldg(map + ab[k] + 4) : 0.0f;
            ex[k][1] = need ? __ldg(map + ab[k] + GDIM + 4) : 0.0f;
            ex[k][2] = need ? __ldg(map + ab[k] + GD2 + 4) : 0.0f;
            ex[k][3] = need ? __ldg(map + ab[k] + GD2 + GDIM + 4) : 0.0f;
        }

        // --- consume ---
        #pragma unroll
        for (int k = 0; k < 2; k++) {
            const int p = ph[k];
            float lo[4], hi[4];
            #pragma unroll
            for (int r = 0; r < 4; r++) {
                const float4 v = q[k][r];
                lo[r] = (p == 0) ? v.x : (p == 1) ? v.y : (p == 2) ? v.z : v.w;
                hi[r] = (p == 0) ? v.y : (p == 1) ? v.z : (p == 2) ? v.w
                                                                   : ex[k][r];
            }
            const float omx = 1.0f - fx[k], omy = 1.0f - fy[k];
            const float l0 = (lo[0] * omx + hi[0] * fx[k]) * omy
                           + (lo[1] * omx + hi[1] * fx[k]) * fy[k];
            const float l1 = (lo[2] * omx + hi[2] * fx[k]) * omy
                           + (lo[3] * omx + hi[3] * fx[k]) * fy[k];
            const float dist = l0 * (1.0f - fz[k]) + l1 * fz[k];
            const float cost = valid[k] ? __expf(-(dist - 0.6f) * (1.0f / 0.3f))
                                        : 0.0f;
            w += 0.2f * fmaxf(0.2f - cost, 0.0f);
        }

        if (s0 == 0) w += 0.5f * p4.w;   // fold pitch term once
        sC[tid] = w;
    }
    __syncthreads();

    if (tid < TRAJ) {
        float v = 0.0f;
        #pragma unroll
        for (int k = 0; k < NT; k++) v += sC[tid * NT + k];
        atomicAdd(&out[o * TRAJ + tid], v);
    }
}

extern "C" void kernel_launch(void* const* d_in, const int* in_sizes, int n_in,
                              void* d_out, int out_size)
{
    const float* Df     = (const float*)d_in[0];
    const float* Dp     = (const float*)d_in[1];
    const float* goal   = (const float*)d_in[2];
    const float* L      = (const float*)d_in[3];
    const float* sdf    = (const float*)d_in[4];
    const float* minb   = (const float*)d_in[5];
    const int*   map_id = (const int*)d_in[6];
    float* out = (float*)d_out;

    const int outer = in_sizes[6];
    const int n_bt  = outer * TRAJ * NT;

    prelude_kernel<<<(n_bt + 255) / 256, 256>>>(Df, Dp, goal, L, minb, map_id,
                                                out, n_bt);
    dim3 grid(NS / 2, outer);
    gather_kernel<<<grid, 256>>>(sdf, map_id, out);
}

// round 12
// speedup vs baseline: 1.0135x; 1.0135x over previous
#include <cuda_runtime.h>
#include <cuda_bf16.h>
#include <cstdint>

#define TRAJ      25
#define NT        10
#define NS        10
#define GDIM      200
#define GD2       (GDIM * GDIM)
#define MAP_ELEMS 8000000
#define VFOV_C    0.3490658503988659f
#define MAX_BT    (1024 * TRAJ * NT)   // supports outer up to 1024

// Interleaved staging: [n*2+0] = (pos_voxel.xyz, pen), [n*2+1] = (gdir.xyz, 0)
__device__ float4 g_stage[MAX_BT * 2];

// ---------- kernel 1: per-(b,t) prelude ----------
__global__ __launch_bounds__(256) void prelude_kernel(
    const float* __restrict__ Df, const float* __restrict__ Dp,
    const float* __restrict__ goal, const float* __restrict__ L,
    const float* __restrict__ minb, const int* __restrict__ map_id,
    float* __restrict__ out, int n_bt)
{
    const int n = blockIdx.x * blockDim.x + threadIdx.x;
    if (n >= n_bt) return;
    const int b  = n / NT;
    const int it = n - b * NT;
    const int o  = b / TRAJ;

    const float t = 0.66f + (float)it * ((1.32f - 0.66f) / 9.0f);

    float pos[3], vel[3];
    #pragma unroll
    for (int c = 0; c < 3; c++) {
        const float d0 = __ldg(Df + b * 9 + c * 3 + 0);
        const float d1 = __ldg(Df + b * 9 + c * 3 + 1);
        const float d2 = __ldg(Df + b * 9 + c * 3 + 2);
        const float d3 = __ldg(Dp + b * 9 + c * 3 + 0);
        const float d4 = __ldg(Dp + b * 9 + c * 3 + 1);
        const float d5 = __ldg(Dp + b * 9 + c * 3 + 2);
        float coe[6];
        #pragma unroll
        for (int i = 0; i < 6; i++) {
            coe[i] = __ldg(L + i * 6 + 0) * d0 + __ldg(L + i * 6 + 1) * d1
                   + __ldg(L + i * 6 + 2) * d2 + __ldg(L + i * 6 + 3) * d3
                   + __ldg(L + i * 6 + 4) * d4 + __ldg(L + i * 6 + 5) * d5;
        }
        float p = coe[5];
        p = p * t + coe[4];
        p = p * t + coe[3];
        p = p * t + coe[2];
        p = p * t + coe[1];
        p = p * t + coe[0];
        pos[c] = p;
        float v = 5.0f * coe[5];
        v = v * t + 4.0f * coe[4];
        v = v * t + 3.0f * coe[3];
        v = v * t + 2.0f * coe[2];
        v = v * t + coe[1];
        vel[c] = v;
    }

    const float gx0 = __ldg(goal + (long long)o * TRAJ * 3 + 0);
    const float gy0 = __ldg(goal + (long long)o * TRAJ * 3 + 1);
    const float gz0 = __ldg(goal + (long long)o * TRAJ * 3 + 2);
    const float gdx = gx0 - pos[0];
    const float gdy = gy0 - pos[1];
    const float gdz = gz0 - pos[2];

    const float pg = atan2f(gdz, sqrtf(gdx * gdx + gdy * gdy + 1e-6f));
    const float pv = atan2f(vel[2], sqrtf(vel[0] * vel[0] + vel[1] * vel[1] + 1e-6f));
    const float pen = fmaxf(fabsf(pg - pv) - VFOV_C, 0.0f);

    const int   m   = __ldg(map_id + o);
    const float mb0 = __ldg(minb + m * 3 + 0);
    const float mb1 = __ldg(minb + m * 3 + 1);
    const float mb2 = __ldg(minb + m * 3 + 2);

    g_stage[n * 2 + 0] = make_float4((pos[0] - mb0) * 5.0f,
                                     (pos[1] - mb1) * 5.0f,
                                     (pos[2] - mb2) * 5.0f, pen);
    g_stage[n * 2 + 1] = make_float4(gdx * 5.0f, gdy * 5.0f, gdz * 5.0f, 0.0f);

    if (it == 0) out[b] = 0.0f;   // zero-init before gather kernel's atomics
}

// ---------- kernel 2: TWO samples/thread, float2 corner loads ----------
// grid (outer, NS/2); tid<250 -> (traj j, time it); samples s0, s0+5.
// float2 x-pair loads keep register footprint low (~48) so occupancy stays
// ~60% while depth doubles: ~560 independent lines in flight per SM.
__global__ __launch_bounds__(256) void gather_kernel(
    const float* __restrict__ sdf, const int* __restrict__ map_id,
    float* __restrict__ out)
{
    const int o   = blockIdx.x;
    const int s0  = blockIdx.y;          // samples s0 and s0+5
    const int tid = threadIdx.x;

    __shared__ float sC[TRAJ * NT];

    float w = 0.0f;
    if (tid < TRAJ * NT) {
        const int n = (o * TRAJ) * NT + tid;

        const float4 p4 = __ldg(g_stage + n * 2 + 0);
        const float4 g4 = __ldg(g_stage + n * 2 + 1);

        const float* __restrict__ map =
            sdf + (long long)__ldg(map_id + o) * MAP_ELEMS;

        // --- coordinates / 8B-aligned bases for both samples ---
        float fx[2], fy[2], fz[2];
        bool  valid[2], odd[2];
        int   ab[2];
        #pragma unroll
        for (int k = 0; k < 2; k++) {
            const float a  = (float)(s0 + 5 * k) * (1.0f / 9.0f);
            const float vx = p4.x + a * g4.x;
            const float vy = p4.y + a * g4.y;
            const float vz = p4.z + a * g4.z;
            valid[k] = (vx > 0.5f) && (vx < (float)GDIM - 1.5f)
                    && (vy > 0.5f) && (vy < (float)GDIM - 1.5f)
                    && (vz > 0.5f) && (vz < (float)GDIM - 1.5f);
            const float x0f = fminf(fmaxf(floorf(vx), 0.0f), (float)(GDIM - 2));
            const float y0f = fminf(fmaxf(floorf(vy), 0.0f), (float)(GDIM - 2));
            const float z0f = fminf(fmaxf(floorf(vz), 0.0f), (float)(GDIM - 2));
            fx[k] = vx - x0f; fy[k] = vy - y0f; fz[k] = vz - z0f;
            const int x0 = valid[k] ? (int)x0f : 0;
            const int y0 = valid[k] ? (int)y0f : 0;
            const int z0 = valid[k] ? (int)z0f : 0;
            odd[k] = (x0 & 1);
            ab[k]  = z0 * GD2 + y0 * GDIM + (x0 & ~1);
        }

        // --- issue ALL gathers back-to-back (8 float2 + predicated patch) ---
        float2 q[2][4];
        float  e[2][4];
        #pragma unroll
        for (int k = 0; k < 2; k++) {
            q[k][0] = __ldg((const float2*)(map + ab[k]));
            q[k][1] = __ldg((const float2*)(map + ab[k] + GDIM));
            q[k][2] = __ldg((const float2*)(map + ab[k] + GD2));
            q[k][3] = __ldg((const float2*)(map + ab[k] + GD2 + GDIM));
        }
        #pragma unroll
        for (int k = 0; k < 2; k++) {
            e[k][0] = odd[k] ? __ldg(map + ab[k] + 2) : 0.0f;
            e[k][1] = odd[k] ? __ldg(map + ab[k] + GDIM + 2) : 0.0f;
            e[k][2] = odd[k] ? __ldg(map + ab[k] + GD2 + 2) : 0.0f;
            e[k][3] = odd[k] ? __ldg(map + ab[k] + GD2 + GDIM + 2) : 0.0f;
        }

        // --- consume ---
        #pragma unroll
        for (int k = 0; k < 2; k++) {
            float lo[4], hi[4];
            #pragma unroll
            for (int r = 0; r < 4; r++) {
                lo[r] = odd[k] ? q[k][r].y : q[k][r].x;
                hi[r] = odd[k] ? e[k][r]   : q[k][r].y;
            }
            const float omx = 1.0f - fx[k], omy = 1.0f - fy[k];
            const float l0 = (lo[0] * omx + hi[0] * fx[k]) * omy
                           + (lo[1] * omx + hi[1] * fx[k]) * fy[k];
            const float l1 = (lo[2] * omx + hi[2] * fx[k]) * omy
                           + (lo[3] * omx + hi[3] * fx[k]) * fy[k];
            const float dist = l0 * (1.0f - fz[k]) + l1 * fz[k];
            const float cost = valid[k] ? __expf(-(dist - 0.6f) * (1.0f / 0.3f))
                                        : 0.0f;
            w += 0.2f * fmaxf(0.2f - cost, 0.0f);
        }

        if (s0 == 0) w += 0.5f * p4.w;   // fold pitch term once
        sC[tid] = w;
    }
    __syncthreads();

    if (tid < TRAJ) {
        float v = 0.0f;
        #pragma unroll
        for (int k = 0; k < NT; k++) v += sC[tid * NT + k];
        atomicAdd(&out[o * TRAJ + tid], v);
    }
}

extern "C" void kernel_launch(void* const* d_in, const int* in_sizes, int n_in,
                              void* d_out, int out_size)
{
    const float* Df     = (const float*)d_in[0];
    const float* Dp     = (const float*)d_in[1];
    const float* goal   = (const float*)d_in[2];
    const float* L      = (const float*)d_in[3];
    const float* sdf    = (const float*)d_in[4];
    const float* minb   = (const float*)d_in[5];
    const int*   map_id = (const int*)d_in[6];
    float* out = (float*)d_out;

    const int outer = in_sizes[6];
    const int n_bt  = outer * TRAJ * NT;

    prelude_kernel<<<(n_bt + 255) / 256, 256>>>(Df, Dp, goal, L, minb, map_id,
                                                out, n_bt);
    dim3 grid(outer, NS / 2);
    gather_kernel<<<grid, 256>>>(sdf, map_id, out);
}